// round 16
// baseline (speedup 1.0000x reference)
#include <cuda_runtime.h>
#include <cuda_fp16.h>
#include <math.h>
#include <stdint.h>

#define RTOT 65536
#define CD   768
#define EPS  1e-5f

// ---------------- scratch (static __device__, allocation-free) --------------
__device__ __half g_xh  [RTOT*CD];     // LN1 out (windowed order), fp16
__device__ __half g_gsum[RTOT*256];    // green+blue, unique content (33MB)
__device__ __half g_qh  [RTOT*CD];
__device__ __half g_kh  [RTOT*CD];
__device__ __half g_vh  [RTOT*CD];
__device__ __half g_ath [RTOT*CD];     // attention out
__device__ __half g_wh  [4*589824];    // fp16 weights: Wq,Wk,Wv,Wp
__device__ float  g_red [RTOT*4];      // per-row {S1,S2,S3,pad} for LN2+MLP
__device__ float  g_wt  [CD];          // n2g*f1w
__device__ float  g_s45 [2];           // {S4, S5}

// ---------------- helpers ---------------------------------------------------
__device__ __forceinline__ void cp16(void* dst, const void* src) {
    unsigned d = (unsigned)__cvta_generic_to_shared(dst);
    asm volatile("cp.async.cg.shared.global [%0], [%1], 16;\n" :: "r"(d), "l"(src));
}
__device__ __forceinline__ void ldsm4(unsigned &r0, unsigned &r1, unsigned &r2, unsigned &r3, unsigned a) {
    asm volatile("ldmatrix.sync.aligned.m8n8.x4.shared.b16 {%0,%1,%2,%3}, [%4];"
                 : "=r"(r0), "=r"(r1), "=r"(r2), "=r"(r3) : "r"(a));
}
__device__ __forceinline__ void ldsm4t(unsigned &r0, unsigned &r1, unsigned &r2, unsigned &r3, unsigned a) {
    asm volatile("ldmatrix.sync.aligned.m8n8.x4.trans.shared.b16 {%0,%1,%2,%3}, [%4];"
                 : "=r"(r0), "=r"(r1), "=r"(r2), "=r"(r3) : "r"(a));
}
__device__ __forceinline__ void mma16816(float* c, const unsigned* a, const unsigned* b) {
    asm volatile(
        "mma.sync.aligned.m16n8k16.row.col.f32.f16.f16.f32 "
        "{%0,%1,%2,%3}, {%4,%5,%6,%7}, {%8,%9}, {%0,%1,%2,%3};\n"
        : "+f"(c[0]), "+f"(c[1]), "+f"(c[2]), "+f"(c[3])
        : "r"(a[0]), "r"(a[1]), "r"(a[2]), "r"(a[3]), "r"(b[0]), "r"(b[1]));
}
__device__ __forceinline__ unsigned packh2(float x, float y) {
    __half2 h = __floats2half2_rn(x, y);
    return *reinterpret_cast<unsigned*>(&h);
}
__device__ __forceinline__ uint32_t s2u(const void* p) {
    return (uint32_t)__cvta_generic_to_shared(p);
}

// ---------------------------------------------------------------------------
// Kernel A (merged): blocks 0..65535 = LN1+window partition (one row each);
// blocks 65536..68607 = weight fp32->fp16 conversion. 192 threads.
// ---------------------------------------------------------------------------
__global__ __launch_bounds__(192) void k_lnw(const float* __restrict__ x,
                                             const float* __restrict__ g,
                                             const float* __restrict__ b,
                                             const float* __restrict__ qkv,
                                             const float* __restrict__ proj) {
    int bid = blockIdx.x;
    int tid = threadIdx.x;

    if (bid >= RTOT) {
        // ---- weight conversion: 3072 blocks x 192 threads = 589824 float4s
        int i = (bid - RTOT) * 192 + tid;
        float4 v = (i < 442368) ? ((const float4*)qkv)[i]
                                : ((const float4*)proj)[i - 442368];
        ((uint2*)g_wh)[i] = make_uint2(packh2(v.x, v.y), packh2(v.z, v.w));
        return;
    }

    // ---- LN1 row
    int wr  = bid;
    int win = wr >> 6, t = wr & 63;
    int bb  = win >> 8, rem = win & 255;
    int wh  = rem >> 4, ww = rem & 15;
    int ii  = t >> 3,  jj = t & 7;
    int sr  = bb * 16384 + (wh * 8 + ii) * 128 + ww * 8 + jj;

    float4 v = ((const float4*)(x + (size_t)sr * CD))[tid];
    float ls = v.x + v.y + v.z + v.w;
    float lq = v.x*v.x + v.y*v.y + v.z*v.z + v.w*v.w;
    #pragma unroll
    for (int o = 16; o > 0; o >>= 1) {
        ls += __shfl_xor_sync(0xffffffffu, ls, o);
        lq += __shfl_xor_sync(0xffffffffu, lq, o);
    }
    __shared__ float ss[6], sq[6];
    int wid = tid >> 5;
    if ((tid & 31) == 0) { ss[wid] = ls; sq[wid] = lq; }
    __syncthreads();
    float S = 0.f, Q = 0.f;
    #pragma unroll
    for (int k = 0; k < 6; k++) { S += ss[k]; Q += sq[k]; }
    float m   = S * (1.f / 768.f);
    float var = Q * (1.f / 768.f) - m * m;
    float inv = rsqrtf(var + EPS);

    float4 gg = ((const float4*)g)[tid];
    float4 bbv = ((const float4*)b)[tid];
    float o0 = (v.x - m) * inv * gg.x + bbv.x;
    float o1 = (v.y - m) * inv * gg.y + bbv.y;
    float o2 = (v.z - m) * inv * gg.z + bbv.z;
    float o3 = (v.w - m) * inv * gg.w + bbv.w;
    ((uint2*)(g_xh + (size_t)wr * CD))[tid] =
        make_uint2(packh2(o0, o1), packh2(o2, o3));
}

// ---------------------------------------------------------------------------
// Kernel B (merged): blocks 0..8191 = gsum (green+blue, 16B/thread);
// blocks 8192..8447 = zero g_red; block 8448 = wt/S4/S5. 256 threads.
// ---------------------------------------------------------------------------
__global__ void k_gsp(const float* __restrict__ n2g, const float* __restrict__ n2b,
                      const float* __restrict__ f1w) {
    int bid = blockIdx.x;
    int tid = threadIdx.x;

    if (bid < 8192) {
        int idx = bid * 256 + tid;
        int rho = idx >> 5;
        int w   = idx & 31;
        int g1 = 65536 + rho, g2 = 131072 + rho;
        const uint4* s1 = (const uint4*)(g_xh + (size_t)(g1 / 3) * CD + (g1 % 3) * 256 + w * 8);
        const uint4* s2 = (const uint4*)(g_xh + (size_t)(g2 / 3) * CD + (g2 % 3) * 256 + w * 8);
        uint4 a = *s1, c = *s2;
        __half2* pa = (__half2*)&a;
        __half2* pc = (__half2*)&c;
        uint4 o;
        __half2* po = (__half2*)&o;
        #pragma unroll
        for (int j = 0; j < 4; j++) po[j] = __hadd2(pa[j], pc[j]);
        *(uint4*)(g_gsum + (size_t)rho * 256 + w * 8) = o;
        return;
    }
    if (bid < 8448) {
        ((float4*)g_red)[(bid - 8192) * 256 + tid] = make_float4(0.f, 0.f, 0.f, 0.f);
        return;
    }
    // ---- wt / S4 / S5
    float s4 = 0.f, s5 = 0.f;
    #pragma unroll
    for (int u = 0; u < 3; u++) {
        int c = tid + 256 * u;
        float wt = n2g[c] * f1w[c];
        g_wt[c] = wt;
        s4 += wt;
        s5 += n2b[c] * f1w[c];
    }
    #pragma unroll
    for (int o = 16; o > 0; o >>= 1) {
        s4 += __shfl_xor_sync(0xffffffffu, s4, o);
        s5 += __shfl_xor_sync(0xffffffffu, s5, o);
    }
    __shared__ float a4[8], a5[8];
    if ((tid & 31) == 0) { a4[tid >> 5] = s4; a5[tid >> 5] = s5; }
    __syncthreads();
    if (tid == 0) {
        float S4 = 0.f, S5 = 0.f;
        #pragma unroll
        for (int k = 0; k < 8; k++) { S4 += a4[k]; S5 += a5[k]; }
        g_s45[0] = S4; g_s45[1] = S5;
    }
}

// ---------------------------------------------------------------------------
// Kernel 3: fp16 tensor GEMM family (unchanged from R15 — verified).
// MODE 1 (QKV): grid.z = {0:Q, 1:K, 2:V}. z==0 -> A=gather(g_gsum),
//   out g_qh scaled by 0.125; z>0 -> A=gather(g_xh red), out g_kh/g_vh.
// MODE 2 (proj): A=g_ath; epilogue reduces (acc+bias) into g_red atomics.
// ---------------------------------------------------------------------------
template<int MODE>
__global__ __launch_bounds__(256, 2) void k_gemm(int wOffBase,
                                                 const float* __restrict__ bias) {
    extern __shared__ __align__(16) __half smh[];   // 3 stages x 16384 halves
    int z = (MODE == 1) ? blockIdx.z : 0;
    const __half* W = g_wh + wOffBase + z * 589824;
    __half* Ch = (MODE == 1) ? (z == 0 ? g_qh : (z == 1 ? g_kh : g_vh)) : nullptr;

    int tid  = threadIdx.x;
    int lane = tid & 31, wid = tid >> 5;
    int wm = wid & 3, wn = wid >> 2;
    int m0 = blockIdx.y * 128, n0 = blockIdx.x * 128;
    int g  = lane >> 2, tg = lane & 3;
    int mA = lane >> 3;

    int frow = tid >> 1;
    int gpar = tid & 1;
    const __half* Wrow = W + (size_t)(n0 + frow) * CD;

    auto fill = [&](int s, int k0) {
        __half* As = smh + s * 16384;
        __half* Bs = As + 8192;
        const __half* Asrc;
        if (MODE == 1) {
            int cb  = k0 >> 8;
            int rho = (3 * (m0 + frow) + cb) & 65535;
            if (z == 0) {
                Asrc = g_gsum + (size_t)rho * 256 + (k0 & 255);
            } else {
                Asrc = g_xh + (size_t)(rho / 3) * CD + (rho % 3) * 256 + (k0 & 255);
            }
        } else {
            Asrc = g_ath + (size_t)(m0 + frow) * CD + k0;
        }
        #pragma unroll
        for (int j = 0; j < 4; j++) {
            int gr = gpar + 2 * j;
            int sw = gr ^ (frow & 7);
            cp16(As + frow * 64 + sw * 8, Asrc + gr * 8);
            cp16(Bs + frow * 64 + sw * 8, Wrow + k0 + gr * 8);
        }
    };

    float acc[2][8][4];
    #pragma unroll
    for (int i = 0; i < 2; i++)
        #pragma unroll
        for (int j = 0; j < 8; j++)
            #pragma unroll
            for (int c = 0; c < 4; c++) acc[i][j][c] = 0.f;

    fill(0, 0);
    asm volatile("cp.async.commit_group;\n");
    fill(1, 64);
    asm volatile("cp.async.commit_group;\n");

    #pragma unroll
    for (int kt = 0; kt < 12; kt++) {
        if (kt < 11) asm volatile("cp.async.wait_group 1;\n");
        else         asm volatile("cp.async.wait_group 0;\n");
        __syncthreads();

        if (kt + 2 < 12) {
            fill((kt + 2) % 3, (kt + 2) * 64);
            asm volatile("cp.async.commit_group;\n");
        }

        unsigned aBase = s2u(smh + (kt % 3) * 16384);
        unsigned bBase = aBase + 16384u;

        #pragma unroll
        for (int kc = 0; kc < 4; kc++) {
            unsigned afr[2][4];
            #pragma unroll
            for (int im = 0; im < 2; im++) {
                int row = wm * 32 + im * 16 + (mA & 1) * 8 + (lane & 7);
                int gr  = kc * 2 + (mA >> 1);
                int sw  = gr ^ (row & 7);
                ldsm4(afr[im][0], afr[im][1], afr[im][2], afr[im][3],
                      aBase + (unsigned)(row * 64 + sw * 8) * 2u);
            }
            unsigned bfr[8][2];
            #pragma unroll
            for (int pr = 0; pr < 4; pr++) {
                int n  = wn * 64 + pr * 16 + ((lane >> 4) * 8) + (lane & 7);
                int kg = kc * 2 + ((lane >> 3) & 1);
                int sw = kg ^ (n & 7);
                unsigned r0, r1, r2, r3;
                ldsm4(r0, r1, r2, r3, bBase + (unsigned)(n * 64 + sw * 8) * 2u);
                bfr[pr*2][0] = r0; bfr[pr*2][1] = r1;
                bfr[pr*2+1][0] = r2; bfr[pr*2+1][1] = r3;
            }
            #pragma unroll
            for (int im = 0; im < 2; im++)
                #pragma unroll
                for (int in_ = 0; in_ < 8; in_++)
                    mma16816(acc[im][in_], afr[im], bfr[in_]);
        }
    }

    if (MODE == 1) {
        const float sc = (z == 0) ? 0.125f : 1.0f;   // fold softmax scale into Q
        #pragma unroll
        for (int im = 0; im < 2; im++) {
            int row = m0 + wm * 32 + im * 16 + g;
            #pragma unroll
            for (int in_ = 0; in_ < 8; in_++) {
                int col = n0 + wn * 64 + in_ * 8 + 2 * tg;
                *reinterpret_cast<unsigned*>(&Ch[(size_t)row * CD + col]) =
                    packh2(acc[im][in_][0] * sc, acc[im][in_][1] * sc);
                *reinterpret_cast<unsigned*>(&Ch[(size_t)(row + 8) * CD + col]) =
                    packh2(acc[im][in_][2] * sc, acc[im][in_][3] * sc);
            }
        }
    } else {
        #pragma unroll
        for (int im = 0; im < 2; im++) {
            float s1a = 0.f, s2a = 0.f, s3a = 0.f;   // row
            float s1b = 0.f, s2b = 0.f, s3b = 0.f;   // row+8
            #pragma unroll
            for (int in_ = 0; in_ < 8; in_++) {
                int col = n0 + wn * 64 + in_ * 8 + 2 * tg;
                float b0 = bias[col], b1 = bias[col + 1];
                float w0 = g_wt[col], w1 = g_wt[col + 1];
                float v0 = acc[im][in_][0] + b0, v1 = acc[im][in_][1] + b1;
                float v2 = acc[im][in_][2] + b0, v3 = acc[im][in_][3] + b1;
                s1a += v0 + v1;  s2a += v0*v0 + v1*v1;  s3a += v0*w0 + v1*w1;
                s1b += v2 + v3;  s2b += v2*v2 + v3*v3;  s3b += v2*w0 + v3*w1;
            }
            #pragma unroll
            for (int o = 1; o < 4; o <<= 1) {
                s1a += __shfl_xor_sync(0xffffffffu, s1a, o);
                s2a += __shfl_xor_sync(0xffffffffu, s2a, o);
                s3a += __shfl_xor_sync(0xffffffffu, s3a, o);
                s1b += __shfl_xor_sync(0xffffffffu, s1b, o);
                s2b += __shfl_xor_sync(0xffffffffu, s2b, o);
                s3b += __shfl_xor_sync(0xffffffffu, s3b, o);
            }
            if (tg == 0) {
                int rowA = m0 + wm * 32 + im * 16 + g;
                atomicAdd(&g_red[rowA * 4 + 0], s1a);
                atomicAdd(&g_red[rowA * 4 + 1], s2a);
                atomicAdd(&g_red[rowA * 4 + 2], s3a);
                atomicAdd(&g_red[(rowA + 8) * 4 + 0], s1b);
                atomicAdd(&g_red[(rowA + 8) * 4 + 1], s2b);
                atomicAdd(&g_red[(rowA + 8) * 4 + 2], s3b);
            }
        }
    }
}

// ---------------------------------------------------------------------------
// Kernel 4: attention (unchanged from R15), block per (window, head).
// ---------------------------------------------------------------------------
__global__ __launch_bounds__(128) void k_attn() {
    __shared__ __half Qs[64 * 72], Ks[64 * 72], Vs[64 * 72];
    int win = blockIdx.x, hd = blockIdx.y;
    int r0 = win * 64, co = hd * 64;
    int tid = threadIdx.x, lane = tid & 31, wid = tid >> 5;
    int g = lane >> 2, tg = lane & 3;
    int mA = lane >> 3;

    {
        int row = tid >> 1, gp = tid & 1;
        size_t gbase = (size_t)(r0 + row) * CD + co;
        const __half* qs = g_qh + gbase;
        const __half* ks = g_kh + gbase;
        const __half* vs = g_vh + gbase;
        #pragma unroll
        for (int j = 0; j < 4; j++) {
            int gr = gp + 2 * j;
            cp16(Qs + row * 72 + gr * 8, qs + gr * 8);
            cp16(Ks + row * 72 + gr * 8, ks + gr * 8);
        }
        asm volatile("cp.async.commit_group;\n");
        #pragma unroll
        for (int j = 0; j < 4; j++) {
            int gr = gp + 2 * j;
            cp16(Vs + row * 72 + gr * 8, vs + gr * 8);
        }
        asm volatile("cp.async.commit_group;\n");
    }
    asm volatile("cp.async.wait_group 1;\n");   // Q,K resident; V in flight
    __syncthreads();

    unsigned qB = (unsigned)__cvta_generic_to_shared(Qs);
    unsigned kB = (unsigned)__cvta_generic_to_shared(Ks);
    unsigned vB = (unsigned)__cvta_generic_to_shared(Vs);

    float sc[8][4];
    #pragma unroll
    for (int j = 0; j < 8; j++)
        #pragma unroll
        for (int c = 0; c < 4; c++) sc[j][c] = 0.f;

    #pragma unroll
    for (int kc = 0; kc < 4; kc++) {
        unsigned afr[4];
        {
            int rr = wid * 16 + (mA & 1) * 8 + (lane & 7);
            ldsm4(afr[0], afr[1], afr[2], afr[3],
                  qB + (unsigned)(rr * 72 + kc * 16 + (mA >> 1) * 8) * 2u);
        }
        unsigned bfr[8][2];
        #pragma unroll
        for (int pr = 0; pr < 4; pr++) {
            int n = pr * 16 + ((lane >> 4) * 8) + (lane & 7);
            unsigned r0_, r1_, r2_, r3_;
            ldsm4(r0_, r1_, r2_, r3_,
                  kB + (unsigned)(n * 72 + kc * 16 + ((lane >> 3) & 1) * 8) * 2u);
            bfr[pr*2][0] = r0_; bfr[pr*2][1] = r1_;
            bfr[pr*2+1][0] = r2_; bfr[pr*2+1][1] = r3_;
        }
        #pragma unroll
        for (int in_ = 0; in_ < 8; in_++)
            mma16816(sc[in_], afr, bfr[in_]);
    }

    float m0 = -1e30f, m1 = -1e30f;
    #pragma unroll
    for (int j = 0; j < 8; j++) {
        m0 = fmaxf(m0, fmaxf(sc[j][0], sc[j][1]));
        m1 = fmaxf(m1, fmaxf(sc[j][2], sc[j][3]));
    }
    #pragma unroll
    for (int o = 1; o < 4; o <<= 1) {
        m0 = fmaxf(m0, __shfl_xor_sync(0xffffffffu, m0, o));
        m1 = fmaxf(m1, __shfl_xor_sync(0xffffffffu, m1, o));
    }
    float s0 = 0.f, s1 = 0.f;
    #pragma unroll
    for (int j = 0; j < 8; j++) {
        sc[j][0] = __expf(sc[j][0] - m0); sc[j][1] = __expf(sc[j][1] - m0);
        sc[j][2] = __expf(sc[j][2] - m1); sc[j][3] = __expf(sc[j][3] - m1);
        s0 += sc[j][0] + sc[j][1];
        s1 += sc[j][2] + sc[j][3];
    }
    #pragma unroll
    for (int o = 1; o < 4; o <<= 1) {
        s0 += __shfl_xor_sync(0xffffffffu, s0, o);
        s1 += __shfl_xor_sync(0xffffffffu, s1, o);
    }
    float i0 = 1.f / s0, i1 = 1.f / s1;
    unsigned p0[8], p1[8];
    #pragma unroll
    for (int j = 0; j < 8; j++) {
        p0[j] = packh2(sc[j][0] * i0, sc[j][1] * i0);
        p1[j] = packh2(sc[j][2] * i1, sc[j][3] * i1);
    }

    asm volatile("cp.async.wait_group 0;\n");   // V resident
    __syncthreads();

    float oc[8][4];
    #pragma unroll
    for (int j = 0; j < 8; j++)
        #pragma unroll
        for (int c = 0; c < 4; c++) oc[j][c] = 0.f;

    #pragma unroll
    for (int kc = 0; kc < 4; kc++) {
        unsigned afr[4] = { p0[2*kc], p1[2*kc], p0[2*kc+1], p1[2*kc+1] };
        unsigned bfr[8][2];
        #pragma unroll
        for (int pr = 0; pr < 4; pr++) {
            int t = kc * 16 + (lane & 7) + 8 * ((lane >> 3) & 1);
            int n = pr * 16 + 8 * (lane >> 4);
            unsigned r0_, r1_, r2_, r3_;
            ldsm4t(r0_, r1_, r2_, r3_, vB + (unsigned)(t * 72 + n) * 2u);
            bfr[pr*2][0] = r0_; bfr[pr*2][1] = r1_;
            bfr[pr*2+1][0] = r2_; bfr[pr*2+1][1] = r3_;
        }
        #pragma unroll
        for (int in_ = 0; in_ < 8; in_++)
            mma16816(oc[in_], afr, bfr[in_]);
    }

    int rowA = r0 + wid * 16 + g;
    #pragma unroll
    for (int in_ = 0; in_ < 8; in_++) {
        int col = co + in_ * 8 + 2 * tg;
        *reinterpret_cast<unsigned*>(&g_ath[(size_t)rowA * CD + col])       = packh2(oc[in_][0], oc[in_][1]);
        *reinterpret_cast<unsigned*>(&g_ath[(size_t)(rowA + 8) * CD + col]) = packh2(oc[in_][2], oc[in_][3]);
    }
}

// ---------------------------------------------------------------------------
// Kernel 5: finalize — read {S1,S2,S3} per row, compute s, gelu, rank-1 out.
// ---------------------------------------------------------------------------
__global__ __launch_bounds__(192) void k_final(const float* __restrict__ f1b,
                                               const float* __restrict__ f2w,
                                               const float* __restrict__ f2b,
                                               float* __restrict__ out) {
    int r = blockIdx.x;
    int tid = threadIdx.x;
    float S1 = g_red[r * 4 + 0];
    float S2 = g_red[r * 4 + 1];
    float S3 = g_red[r * 4 + 2];
    float S4 = g_s45[0], S5 = g_s45[1];

    float m   = S1 * (1.f / 768.f);
    float var = S2 * (1.f / 768.f) - m * m;
    float inv = rsqrtf(var + EPS);
    float s   = (S3 - m * S4) * inv + S5 + f1b[0];
    float hdn = 0.5f * s * (1.f + erff(s * 0.70710678118654752f));

    float4 w = ((const float4*)f2w)[tid];
    float4 b = ((const float4*)f2b)[tid];
    float4 o = make_float4(hdn * w.x + b.x, hdn * w.y + b.y,
                           hdn * w.z + b.z, hdn * w.w + b.w);
    ((float4*)(out + (size_t)r * CD))[tid] = o;
}

// ---------------------------------------------------------------------------
extern "C" void kernel_launch(void* const* d_in, const int* in_sizes, int n_in,
                              void* d_out, int out_size) {
    const float* x     = (const float*)d_in[0];
    const float* n1g   = (const float*)d_in[1];
    const float* n1b   = (const float*)d_in[2];
    const float* n2g   = (const float*)d_in[3];
    const float* n2b   = (const float*)d_in[4];
    const float* qkvw  = (const float*)d_in[5];
    const float* projw = (const float*)d_in[6];
    const float* projb = (const float*)d_in[7];
    const float* f1w   = (const float*)d_in[8];
    const float* f1b   = (const float*)d_in[9];
    const float* f2w   = (const float*)d_in[10];
    const float* f2b   = (const float*)d_in[11];
    float* out = (float*)d_out;

    const int HG_SMEM = 3 * 32768;   // 98304 bytes (2 CTAs/SM)
    cudaFuncSetAttribute(k_gemm<1>, cudaFuncAttributeMaxDynamicSharedMemorySize, HG_SMEM);
    cudaFuncSetAttribute(k_gemm<2>, cudaFuncAttributeMaxDynamicSharedMemorySize, HG_SMEM);

    k_lnw<<<RTOT + 3072, 192>>>(x, n1g, n1b, qkvw, projw);   // LN1 + w2h
    k_gsp<<<8449, 256>>>(n2g, n2b, f1w);                      // gsum + zero + wt

    k_gemm<1><<<dim3(6, 512, 3), 256, HG_SMEM>>>(0,          nullptr);  // Q,K,V

    k_attn<<<dim3(1024, 12), 128>>>();

    k_gemm<2><<<dim3(6, 512),    256, HG_SMEM>>>(3 * 589824, projb);    // proj -> g_red

    k_final<<<RTOT, 192>>>(f1b, f2w, f2b, out);
}

// round 17
// speedup vs baseline: 1.0087x; 1.0087x over previous
#include <cuda_runtime.h>
#include <cuda_fp16.h>
#include <math.h>
#include <stdint.h>

#define RTOT 65536
#define CD   768
#define EPS  1e-5f

// ---------------- scratch (static __device__, allocation-free) --------------
__device__ __half g_xh  [RTOT*CD];     // LN1 out (windowed order), fp16
__device__ __half g_gsum[RTOT*256];    // green+blue, unique content (33MB)
__device__ __half g_qh  [RTOT*CD];
__device__ __half g_kh  [RTOT*CD];
__device__ __half g_vh  [RTOT*CD];
__device__ __half g_ath [RTOT*CD];     // attention out
__device__ __half g_wh  [4*589824];    // fp16 weights: Wq,Wk,Wv,Wp
__device__ float  g_red [RTOT*4];      // per-row {S1,S2,S3,pad} for LN2+MLP
__device__ float  g_wt  [CD];          // n2g*f1w
__device__ float  g_s45 [2];           // {S4, S5}

// ---------------- helpers ---------------------------------------------------
__device__ __forceinline__ void cp16(void* dst, const void* src) {
    unsigned d = (unsigned)__cvta_generic_to_shared(dst);
    asm volatile("cp.async.cg.shared.global [%0], [%1], 16;\n" :: "r"(d), "l"(src));
}
__device__ __forceinline__ void ldsm4(unsigned &r0, unsigned &r1, unsigned &r2, unsigned &r3, unsigned a) {
    asm volatile("ldmatrix.sync.aligned.m8n8.x4.shared.b16 {%0,%1,%2,%3}, [%4];"
                 : "=r"(r0), "=r"(r1), "=r"(r2), "=r"(r3) : "r"(a));
}
__device__ __forceinline__ void ldsm4t(unsigned &r0, unsigned &r1, unsigned &r2, unsigned &r3, unsigned a) {
    asm volatile("ldmatrix.sync.aligned.m8n8.x4.trans.shared.b16 {%0,%1,%2,%3}, [%4];"
                 : "=r"(r0), "=r"(r1), "=r"(r2), "=r"(r3) : "r"(a));
}
__device__ __forceinline__ void mma16816(float* c, const unsigned* a, const unsigned* b) {
    asm volatile(
        "mma.sync.aligned.m16n8k16.row.col.f32.f16.f16.f32 "
        "{%0,%1,%2,%3}, {%4,%5,%6,%7}, {%8,%9}, {%0,%1,%2,%3};\n"
        : "+f"(c[0]), "+f"(c[1]), "+f"(c[2]), "+f"(c[3])
        : "r"(a[0]), "r"(a[1]), "r"(a[2]), "r"(a[3]), "r"(b[0]), "r"(b[1]));
}
__device__ __forceinline__ unsigned packh2(float x, float y) {
    __half2 h = __floats2half2_rn(x, y);
    return *reinterpret_cast<unsigned*>(&h);
}
__device__ __forceinline__ uint32_t s2u(const void* p) {
    return (uint32_t)__cvta_generic_to_shared(p);
}

// ---------------------------------------------------------------------------
// Kernel A (merged): blocks 0..65535 = LN1+window partition (one row each);
// blocks 65536..68607 = weight fp32->fp16 conversion. 192 threads.
// ---------------------------------------------------------------------------
__global__ __launch_bounds__(192) void k_lnw(const float* __restrict__ x,
                                             const float* __restrict__ g,
                                             const float* __restrict__ b,
                                             const float* __restrict__ qkv,
                                             const float* __restrict__ proj) {
    int bid = blockIdx.x;
    int tid = threadIdx.x;

    if (bid >= RTOT) {
        int i = (bid - RTOT) * 192 + tid;
        float4 v = (i < 442368) ? ((const float4*)qkv)[i]
                                : ((const float4*)proj)[i - 442368];
        ((uint2*)g_wh)[i] = make_uint2(packh2(v.x, v.y), packh2(v.z, v.w));
        return;
    }

    int wr  = bid;
    int win = wr >> 6, t = wr & 63;
    int bb  = win >> 8, rem = win & 255;
    int wh  = rem >> 4, ww = rem & 15;
    int ii  = t >> 3,  jj = t & 7;
    int sr  = bb * 16384 + (wh * 8 + ii) * 128 + ww * 8 + jj;

    float4 v = ((const float4*)(x + (size_t)sr * CD))[tid];
    float ls = v.x + v.y + v.z + v.w;
    float lq = v.x*v.x + v.y*v.y + v.z*v.z + v.w*v.w;
    #pragma unroll
    for (int o = 16; o > 0; o >>= 1) {
        ls += __shfl_xor_sync(0xffffffffu, ls, o);
        lq += __shfl_xor_sync(0xffffffffu, lq, o);
    }
    __shared__ float ss[6], sq[6];
    int wid = tid >> 5;
    if ((tid & 31) == 0) { ss[wid] = ls; sq[wid] = lq; }
    __syncthreads();
    float S = 0.f, Q = 0.f;
    #pragma unroll
    for (int k = 0; k < 6; k++) { S += ss[k]; Q += sq[k]; }
    float m   = S * (1.f / 768.f);
    float var = Q * (1.f / 768.f) - m * m;
    float inv = rsqrtf(var + EPS);

    float4 gg = ((const float4*)g)[tid];
    float4 bbv = ((const float4*)b)[tid];
    float o0 = (v.x - m) * inv * gg.x + bbv.x;
    float o1 = (v.y - m) * inv * gg.y + bbv.y;
    float o2 = (v.z - m) * inv * gg.z + bbv.z;
    float o3 = (v.w - m) * inv * gg.w + bbv.w;
    ((uint2*)(g_xh + (size_t)wr * CD))[tid] =
        make_uint2(packh2(o0, o1), packh2(o2, o3));
}

// ---------------------------------------------------------------------------
// Kernel B (merged): blocks 0..8191 = gsum; 8192..8447 zero g_red;
// block 8448 = wt/S4/S5. 256 threads.
// ---------------------------------------------------------------------------
__global__ void k_gsp(const float* __restrict__ n2g, const float* __restrict__ n2b,
                      const float* __restrict__ f1w) {
    int bid = blockIdx.x;
    int tid = threadIdx.x;

    if (bid < 8192) {
        int idx = bid * 256 + tid;
        int rho = idx >> 5;
        int w   = idx & 31;
        int g1 = 65536 + rho, g2 = 131072 + rho;
        const uint4* s1 = (const uint4*)(g_xh + (size_t)(g1 / 3) * CD + (g1 % 3) * 256 + w * 8);
        const uint4* s2 = (const uint4*)(g_xh + (size_t)(g2 / 3) * CD + (g2 % 3) * 256 + w * 8);
        uint4 a = *s1, c = *s2;
        __half2* pa = (__half2*)&a;
        __half2* pc = (__half2*)&c;
        uint4 o;
        __half2* po = (__half2*)&o;
        #pragma unroll
        for (int j = 0; j < 4; j++) po[j] = __hadd2(pa[j], pc[j]);
        *(uint4*)(g_gsum + (size_t)rho * 256 + w * 8) = o;
        return;
    }
    if (bid < 8448) {
        ((float4*)g_red)[(bid - 8192) * 256 + tid] = make_float4(0.f, 0.f, 0.f, 0.f);
        return;
    }
    float s4 = 0.f, s5 = 0.f;
    #pragma unroll
    for (int u = 0; u < 3; u++) {
        int c = tid + 256 * u;
        float wt = n2g[c] * f1w[c];
        g_wt[c] = wt;
        s4 += wt;
        s5 += n2b[c] * f1w[c];
    }
    #pragma unroll
    for (int o = 16; o > 0; o >>= 1) {
        s4 += __shfl_xor_sync(0xffffffffu, s4, o);
        s5 += __shfl_xor_sync(0xffffffffu, s5, o);
    }
    __shared__ float a4[8], a5[8];
    if ((tid & 31) == 0) { a4[tid >> 5] = s4; a5[tid >> 5] = s5; }
    __syncthreads();
    if (tid == 0) {
        float S4 = 0.f, S5 = 0.f;
        #pragma unroll
        for (int k = 0; k < 8; k++) { S4 += a4[k]; S5 += a5[k]; }
        g_s45[0] = S4; g_s45[1] = S5;
    }
}

// ---------------------------------------------------------------------------
// Kernel 3: fp16 tensor GEMM family. Mainloop identical to R15 (verified).
// MODE 1 (QKV): grid (18, 512): z = bx%3 in the FASTEST dim so K and V
//   blocks sharing the same A tile run concurrently (L2 dedup of A reads);
//   m0 reversed (LIFO vs producer writes). z==0 -> A=gather(g_gsum),
//   out g_qh scaled by 0.125; z>0 -> A=gather(g_xh red), out g_kh/g_vh.
// MODE 2 (proj): grid (6,512); A=g_ath; epilogue reduces into g_red atomics.
// ---------------------------------------------------------------------------
template<int MODE>
__global__ __launch_bounds__(256, 2) void k_gemm(int wOffBase,
                                                 const float* __restrict__ bias) {
    extern __shared__ __align__(16) __half smh[];   // 3 stages x 16384 halves
    int z, n0, m0;
    if (MODE == 1) {
        z  = blockIdx.x % 3;
        n0 = (blockIdx.x / 3) * 128;
        m0 = (511 - blockIdx.y) * 128;      // LIFO: read freshest rows first
    } else {
        z  = 0;
        n0 = blockIdx.x * 128;
        m0 = blockIdx.y * 128;
    }
    const __half* W = g_wh + wOffBase + z * 589824;
    __half* Ch = (MODE == 1) ? (z == 0 ? g_qh : (z == 1 ? g_kh : g_vh)) : nullptr;

    int tid  = threadIdx.x;
    int lane = tid & 31, wid = tid >> 5;
    int wm = wid & 3, wn = wid >> 2;
    int g  = lane >> 2, tg = lane & 3;
    int mA = lane >> 3;

    int frow = tid >> 1;
    int gpar = tid & 1;
    const __half* Wrow = W + (size_t)(n0 + frow) * CD;

    auto fill = [&](int s, int k0) {
        __half* As = smh + s * 16384;
        __half* Bs = As + 8192;
        const __half* Asrc;
        if (MODE == 1) {
            int cb  = k0 >> 8;
            int rho = (3 * (m0 + frow) + cb) & 65535;
            if (z == 0) {
                Asrc = g_gsum + (size_t)rho * 256 + (k0 & 255);
            } else {
                Asrc = g_xh + (size_t)(rho / 3) * CD + (rho % 3) * 256 + (k0 & 255);
            }
        } else {
            Asrc = g_ath + (size_t)(m0 + frow) * CD + k0;
        }
        #pragma unroll
        for (int j = 0; j < 4; j++) {
            int gr = gpar + 2 * j;
            int sw = gr ^ (frow & 7);
            cp16(As + frow * 64 + sw * 8, Asrc + gr * 8);
            cp16(Bs + frow * 64 + sw * 8, Wrow + k0 + gr * 8);
        }
    };

    float acc[2][8][4];
    #pragma unroll
    for (int i = 0; i < 2; i++)
        #pragma unroll
        for (int j = 0; j < 8; j++)
            #pragma unroll
            for (int c = 0; c < 4; c++) acc[i][j][c] = 0.f;

    fill(0, 0);
    asm volatile("cp.async.commit_group;\n");
    fill(1, 64);
    asm volatile("cp.async.commit_group;\n");

    #pragma unroll
    for (int kt = 0; kt < 12; kt++) {
        if (kt < 11) asm volatile("cp.async.wait_group 1;\n");
        else         asm volatile("cp.async.wait_group 0;\n");
        __syncthreads();

        if (kt + 2 < 12) {
            fill((kt + 2) % 3, (kt + 2) * 64);
            asm volatile("cp.async.commit_group;\n");
        }

        unsigned aBase = s2u(smh + (kt % 3) * 16384);
        unsigned bBase = aBase + 16384u;

        #pragma unroll
        for (int kc = 0; kc < 4; kc++) {
            unsigned afr[2][4];
            #pragma unroll
            for (int im = 0; im < 2; im++) {
                int row = wm * 32 + im * 16 + (mA & 1) * 8 + (lane & 7);
                int gr  = kc * 2 + (mA >> 1);
                int sw  = gr ^ (row & 7);
                ldsm4(afr[im][0], afr[im][1], afr[im][2], afr[im][3],
                      aBase + (unsigned)(row * 64 + sw * 8) * 2u);
            }
            unsigned bfr[8][2];
            #pragma unroll
            for (int pr = 0; pr < 4; pr++) {
                int n  = wn * 64 + pr * 16 + ((lane >> 4) * 8) + (lane & 7);
                int kg = kc * 2 + ((lane >> 3) & 1);
                int sw = kg ^ (n & 7);
                unsigned r0, r1, r2, r3;
                ldsm4(r0, r1, r2, r3, bBase + (unsigned)(n * 64 + sw * 8) * 2u);
                bfr[pr*2][0] = r0; bfr[pr*2][1] = r1;
                bfr[pr*2+1][0] = r2; bfr[pr*2+1][1] = r3;
            }
            #pragma unroll
            for (int im = 0; im < 2; im++)
                #pragma unroll
                for (int in_ = 0; in_ < 8; in_++)
                    mma16816(acc[im][in_], afr[im], bfr[in_]);
        }
    }

    if (MODE == 1) {
        const float sc = (z == 0) ? 0.125f : 1.0f;   // fold softmax scale into Q
        #pragma unroll
        for (int im = 0; im < 2; im++) {
            int row = m0 + wm * 32 + im * 16 + g;
            #pragma unroll
            for (int in_ = 0; in_ < 8; in_++) {
                int col = n0 + wn * 64 + in_ * 8 + 2 * tg;
                *reinterpret_cast<unsigned*>(&Ch[(size_t)row * CD + col]) =
                    packh2(acc[im][in_][0] * sc, acc[im][in_][1] * sc);
                *reinterpret_cast<unsigned*>(&Ch[(size_t)(row + 8) * CD + col]) =
                    packh2(acc[im][in_][2] * sc, acc[im][in_][3] * sc);
            }
        }
    } else {
        #pragma unroll
        for (int im = 0; im < 2; im++) {
            float s1a = 0.f, s2a = 0.f, s3a = 0.f;
            float s1b = 0.f, s2b = 0.f, s3b = 0.f;
            #pragma unroll
            for (int in_ = 0; in_ < 8; in_++) {
                int col = n0 + wn * 64 + in_ * 8 + 2 * tg;
                float b0 = bias[col], b1 = bias[col + 1];
                float w0 = g_wt[col], w1 = g_wt[col + 1];
                float v0 = acc[im][in_][0] + b0, v1 = acc[im][in_][1] + b1;
                float v2 = acc[im][in_][2] + b0, v3 = acc[im][in_][3] + b1;
                s1a += v0 + v1;  s2a += v0*v0 + v1*v1;  s3a += v0*w0 + v1*w1;
                s1b += v2 + v3;  s2b += v2*v2 + v3*v3;  s3b += v2*w0 + v3*w1;
            }
            #pragma unroll
            for (int o = 1; o < 4; o <<= 1) {
                s1a += __shfl_xor_sync(0xffffffffu, s1a, o);
                s2a += __shfl_xor_sync(0xffffffffu, s2a, o);
                s3a += __shfl_xor_sync(0xffffffffu, s3a, o);
                s1b += __shfl_xor_sync(0xffffffffu, s1b, o);
                s2b += __shfl_xor_sync(0xffffffffu, s2b, o);
                s3b += __shfl_xor_sync(0xffffffffu, s3b, o);
            }
            if (tg == 0) {
                int rowA = m0 + wm * 32 + im * 16 + g;
                atomicAdd(&g_red[rowA * 4 + 0], s1a);
                atomicAdd(&g_red[rowA * 4 + 1], s2a);
                atomicAdd(&g_red[rowA * 4 + 2], s3a);
                atomicAdd(&g_red[(rowA + 8) * 4 + 0], s1b);
                atomicAdd(&g_red[(rowA + 8) * 4 + 1], s2b);
                atomicAdd(&g_red[(rowA + 8) * 4 + 2], s3b);
            }
        }
    }
}

// ---------------------------------------------------------------------------
// Kernel 4: attention (unchanged, verified), block per (window, head).
// ---------------------------------------------------------------------------
__global__ __launch_bounds__(128) void k_attn() {
    __shared__ __half Qs[64 * 72], Ks[64 * 72], Vs[64 * 72];
    int win = blockIdx.x, hd = blockIdx.y;
    int r0 = win * 64, co = hd * 64;
    int tid = threadIdx.x, lane = tid & 31, wid = tid >> 5;
    int g = lane >> 2, tg = lane & 3;
    int mA = lane >> 3;

    {
        int row = tid >> 1, gp = tid & 1;
        size_t gbase = (size_t)(r0 + row) * CD + co;
        const __half* qs = g_qh + gbase;
        const __half* ks = g_kh + gbase;
        const __half* vs = g_vh + gbase;
        #pragma unroll
        for (int j = 0; j < 4; j++) {
            int gr = gp + 2 * j;
            cp16(Qs + row * 72 + gr * 8, qs + gr * 8);
            cp16(Ks + row * 72 + gr * 8, ks + gr * 8);
        }
        asm volatile("cp.async.commit_group;\n");
        #pragma unroll
        for (int j = 0; j < 4; j++) {
            int gr = gp + 2 * j;
            cp16(Vs + row * 72 + gr * 8, vs + gr * 8);
        }
        asm volatile("cp.async.commit_group;\n");
    }
    asm volatile("cp.async.wait_group 1;\n");
    __syncthreads();

    unsigned qB = (unsigned)__cvta_generic_to_shared(Qs);
    unsigned kB = (unsigned)__cvta_generic_to_shared(Ks);
    unsigned vB = (unsigned)__cvta_generic_to_shared(Vs);

    float sc[8][4];
    #pragma unroll
    for (int j = 0; j < 8; j++)
        #pragma unroll
        for (int c = 0; c < 4; c++) sc[j][c] = 0.f;

    #pragma unroll
    for (int kc = 0; kc < 4; kc++) {
        unsigned afr[4];
        {
            int rr = wid * 16 + (mA & 1) * 8 + (lane & 7);
            ldsm4(afr[0], afr[1], afr[2], afr[3],
                  qB + (unsigned)(rr * 72 + kc * 16 + (mA >> 1) * 8) * 2u);
        }
        unsigned bfr[8][2];
        #pragma unroll
        for (int pr = 0; pr < 4; pr++) {
            int n = pr * 16 + ((lane >> 4) * 8) + (lane & 7);
            unsigned r0_, r1_, r2_, r3_;
            ldsm4(r0_, r1_, r2_, r3_,
                  kB + (unsigned)(n * 72 + kc * 16 + ((lane >> 3) & 1) * 8) * 2u);
            bfr[pr*2][0] = r0_; bfr[pr*2][1] = r1_;
            bfr[pr*2+1][0] = r2_; bfr[pr*2+1][1] = r3_;
        }
        #pragma unroll
        for (int in_ = 0; in_ < 8; in_++)
            mma16816(sc[in_], afr, bfr[in_]);
    }

    float m0 = -1e30f, m1 = -1e30f;
    #pragma unroll
    for (int j = 0; j < 8; j++) {
        m0 = fmaxf(m0, fmaxf(sc[j][0], sc[j][1]));
        m1 = fmaxf(m1, fmaxf(sc[j][2], sc[j][3]));
    }
    #pragma unroll
    for (int o = 1; o < 4; o <<= 1) {
        m0 = fmaxf(m0, __shfl_xor_sync(0xffffffffu, m0, o));
        m1 = fmaxf(m1, __shfl_xor_sync(0xffffffffu, m1, o));
    }
    float s0 = 0.f, s1 = 0.f;
    #pragma unroll
    for (int j = 0; j < 8; j++) {
        sc[j][0] = __expf(sc[j][0] - m0); sc[j][1] = __expf(sc[j][1] - m0);
        sc[j][2] = __expf(sc[j][2] - m1); sc[j][3] = __expf(sc[j][3] - m1);
        s0 += sc[j][0] + sc[j][1];
        s1 += sc[j][2] + sc[j][3];
    }
    #pragma unroll
    for (int o = 1; o < 4; o <<= 1) {
        s0 += __shfl_xor_sync(0xffffffffu, s0, o);
        s1 += __shfl_xor_sync(0xffffffffu, s1, o);
    }
    float i0 = 1.f / s0, i1 = 1.f / s1;
    unsigned p0[8], p1[8];
    #pragma unroll
    for (int j = 0; j < 8; j++) {
        p0[j] = packh2(sc[j][0] * i0, sc[j][1] * i0);
        p1[j] = packh2(sc[j][2] * i1, sc[j][3] * i1);
    }

    asm volatile("cp.async.wait_group 0;\n");
    __syncthreads();

    float oc[8][4];
    #pragma unroll
    for (int j = 0; j < 8; j++)
        #pragma unroll
        for (int c = 0; c < 4; c++) oc[j][c] = 0.f;

    #pragma unroll
    for (int kc = 0; kc < 4; kc++) {
        unsigned afr[4] = { p0[2*kc], p1[2*kc], p0[2*kc+1], p1[2*kc+1] };
        unsigned bfr[8][2];
        #pragma unroll
        for (int pr = 0; pr < 4; pr++) {
            int t = kc * 16 + (lane & 7) + 8 * ((lane >> 3) & 1);
            int n = pr * 16 + 8 * (lane >> 4);
            unsigned r0_, r1_, r2_, r3_;
            ldsm4t(r0_, r1_, r2_, r3_, vB + (unsigned)(t * 72 + n) * 2u);
            bfr[pr*2][0] = r0_; bfr[pr*2][1] = r1_;
            bfr[pr*2+1][0] = r2_; bfr[pr*2+1][1] = r3_;
        }
        #pragma unroll
        for (int in_ = 0; in_ < 8; in_++)
            mma16816(oc[in_], afr, bfr[in_]);
    }

    int rowA = r0 + wid * 16 + g;
    #pragma unroll
    for (int in_ = 0; in_ < 8; in_++) {
        int col = co + in_ * 8 + 2 * tg;
        *reinterpret_cast<unsigned*>(&g_ath[(size_t)rowA * CD + col])       = packh2(oc[in_][0], oc[in_][1]);
        *reinterpret_cast<unsigned*>(&g_ath[(size_t)(rowA + 8) * CD + col]) = packh2(oc[in_][2], oc[in_][3]);
    }
}

// ---------------------------------------------------------------------------
// Kernel 5: finalize — read {S1,S2,S3} per row, compute s, gelu, rank-1 out.
// ---------------------------------------------------------------------------
__global__ __launch_bounds__(192) void k_final(const float* __restrict__ f1b,
                                               const float* __restrict__ f2w,
                                               const float* __restrict__ f2b,
                                               float* __restrict__ out) {
    int r = blockIdx.x;
    int tid = threadIdx.x;
    float S1 = g_red[r * 4 + 0];
    float S2 = g_red[r * 4 + 1];
    float S3 = g_red[r * 4 + 2];
    float S4 = g_s45[0], S5 = g_s45[1];

    float m   = S1 * (1.f / 768.f);
    float var = S2 * (1.f / 768.f) - m * m;
    float inv = rsqrtf(var + EPS);
    float s   = (S3 - m * S4) * inv + S5 + f1b[0];
    float hdn = 0.5f * s * (1.f + erff(s * 0.70710678118654752f));

    float4 w = ((const float4*)f2w)[tid];
    float4 b = ((const float4*)f2b)[tid];
    float4 o = make_float4(hdn * w.x + b.x, hdn * w.y + b.y,
                           hdn * w.z + b.z, hdn * w.w + b.w);
    ((float4*)(out + (size_t)r * CD))[tid] = o;
}

// ---------------------------------------------------------------------------
extern "C" void kernel_launch(void* const* d_in, const int* in_sizes, int n_in,
                              void* d_out, int out_size) {
    const float* x     = (const float*)d_in[0];
    const float* n1g   = (const float*)d_in[1];
    const float* n1b   = (const float*)d_in[2];
    const float* n2g   = (const float*)d_in[3];
    const float* n2b   = (const float*)d_in[4];
    const float* qkvw  = (const float*)d_in[5];
    const float* projw = (const float*)d_in[6];
    const float* projb = (const float*)d_in[7];
    const float* f1w   = (const float*)d_in[8];
    const float* f1b   = (const float*)d_in[9];
    const float* f2w   = (const float*)d_in[10];
    const float* f2b   = (const float*)d_in[11];
    float* out = (float*)d_out;

    const int HG_SMEM = 3 * 32768;   // 98304 bytes (2 CTAs/SM)
    cudaFuncSetAttribute(k_gemm<1>, cudaFuncAttributeMaxDynamicSharedMemorySize, HG_SMEM);
    cudaFuncSetAttribute(k_gemm<2>, cudaFuncAttributeMaxDynamicSharedMemorySize, HG_SMEM);

    k_lnw<<<RTOT + 3072, 192>>>(x, n1g, n1b, qkvw, projw);   // LN1 + w2h
    k_gsp<<<8449, 256>>>(n2g, n2b, f1w);                      // gsum + zero + wt

    k_gemm<1><<<dim3(18, 512), 256, HG_SMEM>>>(0,          nullptr);  // Q,K,V (z fastest)

    k_attn<<<dim3(1024, 12), 128>>>();

    k_gemm<2><<<dim3(6, 512),  256, HG_SMEM>>>(3 * 589824, projb);    // proj -> g_red

    k_final<<<RTOT, 192>>>(f1b, f2w, f2b, out);
}